// round 2
// baseline (speedup 1.0000x reference)
#include <cuda_runtime.h>
#include <math.h>

// Problem constants
#define B 256
#define T 96
#define F 368
#define H 368
#define G3 1104          // 3*H
#define NC 29
// output layout: [decisions (B*T)] [coarse_nms (B*T*2)] [fine (B*T*29)]
#define OUT_NMS_OFF   (B*T)          // 24576
#define OUT_FINE_OFF  (B*T + B*T*2)  // 73728

// ---------------- device scratch (no cudaMalloc allowed) ----------------
__device__ float g_xprojT[(size_t)T * G3 * B];      // (t, g, b)  ~108.7 MB
__device__ float g_temporal[(size_t)T * B * H];     // (t, b, h)  ~36 MB
__device__ float g_scores[(size_t)B * T * 2];       // softmax coarse scores

// ---------------- Kernel 1: xproj = feat @ Wi^T + bi, written transposed ----------------
// C[m,g], m = b*T + t  ->  g_xprojT[(t*G3 + g)*B + b]
#define BM 128
#define BN 64
#define BK 16
__global__ __launch_bounds__(256) void xproj_gemm(const float* __restrict__ feat,
                                                  const float* __restrict__ Wi,
                                                  const float* __restrict__ bi) {
    __shared__ float As[BK][BM];
    __shared__ float Ws[BK][BN];
    const int bm = blockIdx.x * BM;
    const int bn = blockIdx.y * BN;
    const int tid = threadIdx.x;
    const int tx = tid % 16;   // n dir, 16*4 = 64
    const int ty = tid / 16;   // m dir, 16*8 = 128

    float acc[8][4];
#pragma unroll
    for (int i = 0; i < 8; i++)
#pragma unroll
        for (int j = 0; j < 4; j++) acc[i][j] = 0.f;

    for (int kt = 0; kt < F; kt += BK) {
        // Load A tile: 128 rows x 16 k = 512 float4, 2 per thread
#pragma unroll
        for (int l = 0; l < 2; l++) {
            int idx = tid + l * 256;
            int m = idx >> 2;
            int kq = idx & 3;
            float4 v = *(const float4*)(feat + (size_t)(bm + m) * F + kt + kq * 4);
            As[kq * 4 + 0][m] = v.x;
            As[kq * 4 + 1][m] = v.y;
            As[kq * 4 + 2][m] = v.z;
            As[kq * 4 + 3][m] = v.w;
        }
        // Load W tile: 64 rows x 16 k = 256 float4, 1 per thread
        {
            int m = tid >> 2;
            int kq = tid & 3;
            int g = bn + m;
            float4 v = make_float4(0.f, 0.f, 0.f, 0.f);
            if (g < G3) v = *(const float4*)(Wi + (size_t)g * F + kt + kq * 4);
            Ws[kq * 4 + 0][m] = v.x;
            Ws[kq * 4 + 1][m] = v.y;
            Ws[kq * 4 + 2][m] = v.z;
            Ws[kq * 4 + 3][m] = v.w;
        }
        __syncthreads();
#pragma unroll
        for (int k = 0; k < BK; k++) {
            float a[8], w[4];
            *(float4*)(a)     = *(const float4*)&As[k][ty * 8];
            *(float4*)(a + 4) = *(const float4*)&As[k][ty * 8 + 4];
            *(float4*)(w)     = *(const float4*)&Ws[k][tx * 4];
#pragma unroll
            for (int i = 0; i < 8; i++)
#pragma unroll
                for (int j = 0; j < 4; j++) acc[i][j] = fmaf(a[i], w[j], acc[i][j]);
        }
        __syncthreads();
    }
    // Epilogue: + bias, scatter to transposed layout
#pragma unroll
    for (int i = 0; i < 8; i++) {
        int m = bm + ty * 8 + i;
        int bb = m / T;
        int tt = m % T;
#pragma unroll
        for (int j = 0; j < 4; j++) {
            int g = bn + tx * 4 + j;
            if (g < G3)
                g_xprojT[((size_t)tt * G3 + g) * B + bb] = acc[i][j] + bi[g];
        }
    }
}

// ---------------- Kernel 2: one GRU step ----------------
// grid 123 blocks: block owns 3 hidden columns j0..j0+2 (all 3 gates).
// 256 threads = batch elements. Wh slice in SMEM, h_prev read as float4 rows.
__global__ __launch_bounds__(256) void gru_step(int t,
                                                const float* __restrict__ Wh,
                                                const float* __restrict__ bhb) {
    __shared__ float ws[9 * H];   // [jj*3+g][k], 13248 B
    const int j0 = blockIdx.x * 3;
    const int tid = threadIdx.x;  // = batch b
    const int b = tid;

    // load Wh slice (rows g*H + j, length H), float4
    for (int q = tid; q < 9 * (H / 4); q += 256) {
        int row = q / (H / 4);
        int kq = q % (H / 4);
        int jj = row / 3;
        int g = row % 3;
        int j = j0 + jj;
        float4 v = make_float4(0.f, 0.f, 0.f, 0.f);
        if (j < H) v = *(const float4*)(Wh + (size_t)(g * H + j) * H + kq * 4);
        *(float4*)&ws[(size_t)row * H + kq * 4] = v;
    }
    __syncthreads();

    float acc[3][3];
#pragma unroll
    for (int jj = 0; jj < 3; jj++) {
        int j = j0 + jj;
#pragma unroll
        for (int g = 0; g < 3; g++)
            acc[jj][g] = (j < H) ? bhb[g * H + j] : 0.f;
    }

    const float* prev = g_temporal + (size_t)(t - 1) * B * H;
    if (t > 0) {
        const float* hrow = prev + (size_t)b * H;
        float4 h4 = *(const float4*)hrow;
#pragma unroll 2
        for (int k4 = 0; k4 < H / 4; k4++) {
            float4 cur = h4;
            if (k4 < H / 4 - 1) h4 = *(const float4*)(hrow + (k4 + 1) * 4);
#pragma unroll
            for (int jj = 0; jj < 3; jj++)
#pragma unroll
                for (int g = 0; g < 3; g++) {
                    float4 wv = *(const float4*)&ws[(size_t)(jj * 3 + g) * H + k4 * 4];
                    acc[jj][g] = fmaf(cur.x, wv.x, acc[jj][g]);
                    acc[jj][g] = fmaf(cur.y, wv.y, acc[jj][g]);
                    acc[jj][g] = fmaf(cur.z, wv.z, acc[jj][g]);
                    acc[jj][g] = fmaf(cur.w, wv.w, acc[jj][g]);
                }
        }
    }

    float* outrow = g_temporal + (size_t)t * B * H + (size_t)b * H;
    const float* xp = g_xprojT + (size_t)t * G3 * B;
#pragma unroll
    for (int jj = 0; jj < 3; jj++) {
        int j = j0 + jj;
        if (j >= H) continue;
        float gi_r = xp[((size_t)0 * H + j) * B + b];
        float gi_z = xp[((size_t)1 * H + j) * B + b];
        float gi_n = xp[((size_t)2 * H + j) * B + b];
        float r = 1.f / (1.f + expf(-(gi_r + acc[jj][0])));
        float z = 1.f / (1.f + expf(-(gi_z + acc[jj][1])));
        float n = tanhf(gi_n + r * acc[jj][2]);
        float hp = (t > 0) ? prev[(size_t)b * H + j] : 0.f;
        outrow[j] = (1.f - z) * n + z * hp;
    }
}

// ---------------- Kernel 3: heads (coarse softmax + fine sigmoid) ----------------
// grid = T blocks, 256 threads = batch. Weights (31 x 368) in SMEM.
__global__ __launch_bounds__(256) void heads_kernel(const float* __restrict__ Wc,
                                                    const float* __restrict__ bc,
                                                    const float* __restrict__ Wf,
                                                    const float* __restrict__ bf,
                                                    float* __restrict__ out) {
    __shared__ float w[31 * H];   // rows: 0-1 Wc, 2-30 Wf; 45632 B
    const int t = blockIdx.x;
    const int tid = threadIdx.x;
    const int b = tid;

    for (int q = tid; q < 31 * (H / 4); q += 256) {
        int row = q / (H / 4);
        int kq = q % (H / 4);
        const float* src = (row < 2) ? (Wc + (size_t)row * H) : (Wf + (size_t)(row - 2) * H);
        *(float4*)&w[(size_t)row * H + kq * 4] = *(const float4*)(src + kq * 4);
    }
    __syncthreads();

    float acc[31];
    acc[0] = bc[0];
    acc[1] = bc[1];
#pragma unroll
    for (int i = 0; i < NC; i++) acc[2 + i] = bf[i];

    const float* hrow = g_temporal + (size_t)t * B * H + (size_t)b * H;
    for (int k4 = 0; k4 < H / 4; k4++) {
        float4 h4 = *(const float4*)(hrow + k4 * 4);
#pragma unroll
        for (int row = 0; row < 31; row++) {
            float4 wv = *(const float4*)&w[(size_t)row * H + k4 * 4];
            acc[row] = fmaf(h4.x, wv.x, acc[row]);
            acc[row] = fmaf(h4.y, wv.y, acc[row]);
            acc[row] = fmaf(h4.z, wv.z, acc[row]);
            acc[row] = fmaf(h4.w, wv.w, acc[row]);
        }
    }

    // coarse softmax (2-way)
    float l0 = acc[0], l1 = acc[1];
    float m = fmaxf(l0, l1);
    float e0 = expf(l0 - m), e1 = expf(l1 - m);
    float inv = 1.f / (e0 + e1);
    size_t idx = (size_t)b * T + t;
    g_scores[idx * 2 + 0] = e0 * inv;
    g_scores[idx * 2 + 1] = e1 * inv;

    // fine sigmoid -> output
    float* fine = out + OUT_FINE_OFF + idx * NC;
#pragma unroll
    for (int i = 0; i < NC; i++) fine[i] = 1.f / (1.f + expf(-acc[2 + i]));
}

// ---------------- Kernel 4: NMS + decisions ----------------
__global__ void nms_kernel(float* __restrict__ out) {
    int idx = blockIdx.x * blockDim.x + threadIdx.x;
    if (idx >= B * T) return;
    int b = idx / T;
    int t = idx % T;
    const float* sb = g_scores + (size_t)b * T * 2;
    float s0 = sb[t * 2 + 0];
    float s1 = sb[t * 2 + 1];
    float wmin = INFINITY;
#pragma unroll
    for (int k = -2; k <= 2; k++) {
        int tt = t + k;
        if (tt >= 0 && tt < T) wmin = fminf(wmin, sb[tt * 2]);
    }
    bool keep = (s0 == wmin);
    float o0 = keep ? s0 : 0.f;
    float o1 = keep ? s1 : 0.f;
    out[idx] = (o1 > o0) ? 1.0f : 0.0f;           // argmax (first index wins ties)
    out[OUT_NMS_OFF + (size_t)idx * 2 + 0] = o0;
    out[OUT_NMS_OFF + (size_t)idx * 2 + 1] = o1;
}

// ---------------- launch ----------------
extern "C" void kernel_launch(void* const* d_in, const int* in_sizes, int n_in,
                              void* d_out, int out_size) {
    const float* feat = (const float*)d_in[0];
    // d_in[1] = hand (unused, matching reference)
    const float* Wi  = (const float*)d_in[2];
    const float* Wh  = (const float*)d_in[3];
    const float* bi  = (const float*)d_in[4];
    const float* bhb = (const float*)d_in[5];
    const float* Wc  = (const float*)d_in[6];
    const float* bc  = (const float*)d_in[7];
    const float* Wf  = (const float*)d_in[8];
    const float* bf  = (const float*)d_in[9];
    float* out = (float*)d_out;

    dim3 g1((B * T) / BM, (G3 + BN - 1) / BN);   // 192 x 18
    xproj_gemm<<<g1, 256>>>(feat, Wi, bi);

    for (int t = 0; t < T; t++)
        gru_step<<<(H + 2) / 3, 256>>>(t, Wh, bhb);   // 123 blocks

    heads_kernel<<<T, 256>>>(Wc, bc, Wf, bf, out);
    nms_kernel<<<(B * T + 255) / 256, 256>>>(out);
}